// round 14
// baseline (speedup 1.0000x reference)
#include <cuda_runtime.h>
#include <cuda_bf16.h>
#include <cstdint>

// Problem constants
#define NMAX 50000
#define EMAX 800000
#define D    128
#define G    512
#define H    64
#define NB_MAX 256   // blocks in scan pass 1 (ceil(50000/256)=196)

// Scratch (static device globals — allowed; runtime alloc is not)
__device__ float    g_hs  [NMAX * D];   // (X@W) * dinv[row]
__device__ float    g_act [NMAX * D];   // final-layer activations (pool input)
__device__ uint32_t g_Xh  [NMAX * D];   // tf32 hi of current GEMM input
__device__ uint32_t g_Xl  [NMAX * D];   // tf32 lo of current GEMM input
__device__ uint32_t g_Wh  [D * D];      // tf32 hi of current layer W
__device__ uint32_t g_Wl  [D * D];      // tf32 lo of current layer W
__device__ float    g_dinv[NMAX];
__device__ float    g_pool[G * D];
__device__ float    g_cnt [G];
// CSR build
__device__ int      g_indeg [NMAX];
__device__ int      g_rowptr[NMAX + 1];
__device__ int      g_cursor[NMAX];
__device__ int      g_csrc  [EMAX];     // src node ids grouped by dst
__device__ int      g_bsum  [NB_MAX];

// ---------------------------------------------------------------------------
// tf32 helpers (mma layout verified R9; split-precision verified R13)
__device__ __forceinline__ uint32_t f2tf32(float f) {
    uint32_t u;
    asm("cvt.rna.tf32.f32 %0, %1;" : "=r"(u) : "f"(f));
    return u;
}

__device__ __forceinline__ void hilo(float f, uint32_t& hi, uint32_t& lo) {
    hi = f2tf32(f);
    lo = f2tf32(f - __uint_as_float(hi));
}

__device__ __forceinline__ void mma_tf32(float c[4],
                                         uint32_t a0, uint32_t a1,
                                         uint32_t a2, uint32_t a3,
                                         uint32_t b0, uint32_t b1) {
    asm volatile(
        "mma.sync.aligned.m16n8k8.row.col.f32.tf32.tf32.f32 "
        "{%0,%1,%2,%3}, {%4,%5,%6,%7}, {%8,%9}, {%0,%1,%2,%3};"
        : "+f"(c[0]), "+f"(c[1]), "+f"(c[2]), "+f"(c[3])
        : "r"(a0), "r"(a1), "r"(a2), "r"(a3), "r"(b0), "r"(b1));
}

// ---------------------------------------------------------------------------
__global__ void init_kernel(int n) {
    int i = blockIdx.x * blockDim.x + threadIdx.x;
    if (i < n) { g_indeg[i] = 0; g_cursor[i] = 0; }
    if (i < G * D)  g_pool[i] = 0.0f;
    if (i < G)      g_cnt[i]  = 0.0f;
}

__global__ void deg_kernel(const int* __restrict__ dst, int E) {
    int e = blockIdx.x * blockDim.x + threadIdx.x;
    if (e < E) atomicAdd(&g_indeg[dst[e]], 1);
}

// ---- scan of g_indeg -> g_rowptr (dinv fused); 2 kernels ------------------
__device__ __forceinline__ int block_scan_excl(int v, int* total) {
    __shared__ int wsum[8];
    int t = threadIdx.x, lane = t & 31, w = t >> 5;
    int x = v;
#pragma unroll
    for (int o = 1; o < 32; o <<= 1) {
        int y = __shfl_up_sync(0xffffffffu, x, o);
        if (lane >= o) x += y;
    }
    if (lane == 31) wsum[w] = x;
    __syncthreads();
    if (w == 0) {
        int s = (lane < 8) ? wsum[lane] : 0;
#pragma unroll
        for (int o = 1; o < 8; o <<= 1) {
            int y = __shfl_up_sync(0xffffffffu, s, o);
            if (lane >= o) s += y;
        }
        if (lane < 8) wsum[lane] = s;
    }
    __syncthreads();
    int incl = x + (w > 0 ? wsum[w - 1] : 0);
    *total = wsum[7];
    return incl - v;
}

__global__ void scan1_kernel(int n) {
    int i = blockIdx.x * 256 + threadIdx.x;
    int v = (i < n) ? g_indeg[i] : 0;
    int total;
    int excl = block_scan_excl(v, &total);
    if (i < n) {
        g_rowptr[i] = excl;
        g_dinv[i] = rsqrtf((float)v + 1.0f);   // + self loop
    }
    if (threadIdx.x == 0) g_bsum[blockIdx.x] = total;
}

// scan3: each block reduces its own bsum prefix (replaces old scan2+scan3)
__global__ void scan3_kernel(int n, int E) {
    __shared__ int red[8];
    int bid = blockIdx.x, t = threadIdx.x, lane = t & 31, w = t >> 5;
    int partial = 0;
    for (int j = t; j < bid; j += 256) partial += g_bsum[j];
#pragma unroll
    for (int o = 16; o > 0; o >>= 1)
        partial += __shfl_down_sync(0xffffffffu, partial, o);
    if (lane == 0) red[w] = partial;
    __syncthreads();
    if (t == 0) {
        int s = 0;
#pragma unroll
        for (int j = 0; j < 8; j++) s += red[j];
        red[0] = s;
    }
    __syncthreads();
    int base = red[0];
    int i = bid * 256 + t;
    if (i < n) g_rowptr[i] += base;
    if (bid == 0 && t == 0) g_rowptr[n] = E;
}

__global__ void fill_kernel(const int* __restrict__ src,
                            const int* __restrict__ dst, int E) {
    int e = blockIdx.x * blockDim.x + threadIdx.x;
    if (e >= E) return;
    int d = dst[e];
    int pos = g_rowptr[d] + atomicAdd(&g_cursor[d], 1);
    g_csrc[pos] = src[e];
}

// ---------------------------------------------------------------------------
// one-time conversions to tf32 hi/lo
__global__ void convert_x_kernel(const float* __restrict__ x, int total4) {
    int i = blockIdx.x * blockDim.x + threadIdx.x;
    if (i >= total4) return;
    float4 v = ((const float4*)x)[i];
    uint4 hv, lv;
    hilo(v.x, hv.x, lv.x);
    hilo(v.y, hv.y, lv.y);
    hilo(v.z, hv.z, lv.z);
    hilo(v.w, hv.w, lv.w);
    ((uint4*)g_Xh)[i] = hv;
    ((uint4*)g_Xl)[i] = lv;
}

__global__ void convert_w_kernel(const float* __restrict__ W) {
    int i = blockIdx.x * blockDim.x + threadIdx.x;   // float4 index, 4096 tot
    float4 v = ((const float4*)W)[i];
    uint4 hv, lv;
    hilo(v.x, hv.x, lv.x);
    hilo(v.y, hv.y, lv.y);
    hilo(v.z, hv.z, lv.z);
    hilo(v.w, hv.w, lv.w);
    ((uint4*)g_Wh)[i] = hv;
    ((uint4*)g_Wl)[i] = lv;
}

// ---------------------------------------------------------------------------
// Split-precision 3xTF32 GEMM: g_hs = (X @ W) * dinv[row]
// Inputs pre-converted to tf32 hi/lo (g_Xh/g_Xl, g_Wh/g_Wl) -> fills are
// pure copies, zero cvt in the hot loop.
// Tile 64(M) x 128(N), 128 threads = 4 warps (2m x 2n), warp tile 32x64.
// K chunked by 16. Smem 25.6KB, occ 4 -> balanced waves (782 tiles/592 slots).
#define TM 64
__global__ void __launch_bounds__(128, 4)
gemm_scale_kernel(int n) {
    // strides 68/132 (== 4 mod 32): fragment LDS bank = 4*t4+tg, conflict-free
    __shared__ uint32_t Xh[16][68], Xl[16][68];     // [k][row] transposed
    __shared__ uint32_t Wh[16][132], Wl[16][132];   // [k][col]

    const int tid  = threadIdx.x;
    const int wid  = tid >> 5;
    const int lane = tid & 31;
    const int tg   = lane >> 2;        // 0..7
    const int t4   = lane & 3;         // 0..3
    const int mw   = wid & 1;          // 2 m-warps
    const int nw   = wid >> 1;         // 2 n-warps
    const int r_base = mw * 32;
    const int n_base = nw * 64;
    const int row0 = blockIdx.x * TM;

    float c[2][8][4];
#pragma unroll
    for (int mt = 0; mt < 2; mt++)
#pragma unroll
        for (int nt = 0; nt < 8; nt++)
#pragma unroll
            for (int i = 0; i < 4; i++) c[mt][nt][i] = 0.0f;

    for (int k0 = 0; k0 < 128; k0 += 16) {
        // X chunk: 64 rows x 16 k transposed; hi+lo: 256 uint4-pairs
#pragma unroll
        for (int i = tid; i < 256; i += 128) {
            int r = i >> 2, q = i & 3;
            uint4 hv = make_uint4(0, 0, 0, 0), lv = make_uint4(0, 0, 0, 0);
            if (row0 + r < n) {
                size_t off = (size_t)(row0 + r) * D + k0 + q * 4;
                hv = *(const uint4*)&g_Xh[off];
                lv = *(const uint4*)&g_Xl[off];
            }
            Xh[q * 4 + 0][r] = hv.x; Xl[q * 4 + 0][r] = lv.x;
            Xh[q * 4 + 1][r] = hv.y; Xl[q * 4 + 1][r] = lv.y;
            Xh[q * 4 + 2][r] = hv.z; Xl[q * 4 + 2][r] = lv.z;
            Xh[q * 4 + 3][r] = hv.w; Xl[q * 4 + 3][r] = lv.w;
        }
        // W chunk: 16 k x 128 cols; pure vector copies
#pragma unroll
        for (int i = tid; i < 512; i += 128) {
            int rk = i >> 5, q = i & 31;
            size_t off = (size_t)(k0 + rk) * D + q * 4;
            *(uint4*)&Wh[rk][q * 4] = *(const uint4*)&g_Wh[off];
            *(uint4*)&Wl[rk][q * 4] = *(const uint4*)&g_Wl[off];
        }
        __syncthreads();

#pragma unroll
        for (int ks = 0; ks < 2; ks++) {
            const int kk = ks * 8 + t4;
            uint32_t ah[2][4], al[2][4];
#pragma unroll
            for (int mt = 0; mt < 2; mt++) {
                int r = r_base + mt * 16 + tg;
                ah[mt][0] = Xh[kk    ][r];     al[mt][0] = Xl[kk    ][r];
                ah[mt][1] = Xh[kk    ][r + 8]; al[mt][1] = Xl[kk    ][r + 8];
                ah[mt][2] = Xh[kk + 4][r];     al[mt][2] = Xl[kk + 4][r];
                ah[mt][3] = Xh[kk + 4][r + 8]; al[mt][3] = Xl[kk + 4][r + 8];
            }
#pragma unroll
            for (int nh = 0; nh < 2; nh++) {
                uint32_t bh[4][2], bl[4][2];
#pragma unroll
                for (int j = 0; j < 4; j++) {
                    int nn = n_base + (nh * 4 + j) * 8 + tg;
                    bh[j][0] = Wh[kk    ][nn]; bl[j][0] = Wl[kk    ][nn];
                    bh[j][1] = Wh[kk + 4][nn]; bl[j][1] = Wl[kk + 4][nn];
                }
#pragma unroll
                for (int mt = 0; mt < 2; mt++)
#pragma unroll
                    for (int j = 0; j < 4; j++) {
                        float* cc = c[mt][nh * 4 + j];
                        mma_tf32(cc, ah[mt][0], ah[mt][1], ah[mt][2], ah[mt][3],
                                 bh[j][0], bh[j][1]);
                        mma_tf32(cc, ah[mt][0], ah[mt][1], ah[mt][2], ah[mt][3],
                                 bl[j][0], bl[j][1]);
                        mma_tf32(cc, al[mt][0], al[mt][1], al[mt][2], al[mt][3],
                                 bh[j][0], bh[j][1]);
                    }
            }
        }
        __syncthreads();
    }

    // Epilogue: scale by dinv[row], write g_hs
#pragma unroll
    for (int mt = 0; mt < 2; mt++) {
        int rA = row0 + r_base + mt * 16 + tg;
        int rB = rA + 8;
        float sA = (rA < n) ? g_dinv[rA] : 0.0f;
        float sB = (rB < n) ? g_dinv[rB] : 0.0f;
#pragma unroll
        for (int nt = 0; nt < 8; nt++) {
            int col = n_base + nt * 8 + t4 * 2;
            if (rA < n)
                *(float2*)&g_hs[(size_t)rA * D + col] =
                    make_float2(c[mt][nt][0] * sA, c[mt][nt][1] * sA);
            if (rB < n)
                *(float2*)&g_hs[(size_t)rB * D + col] =
                    make_float2(c[mt][nt][2] * sB, c[mt][nt][3] * sB);
        }
    }
}

// ---------------------------------------------------------------------------
// Fused gather + activation (pull mode, no atomics).
// to_hilo != 0: write tf32 hi/lo (input of next GEMM); else write fp32 g_act.
__global__ void gather_act_kernel(const float* __restrict__ b, int n,
                                  int to_hilo) {
    int d    = (blockIdx.x * blockDim.x + threadIdx.x) >> 5;
    int lane = threadIdx.x & 31;
    if (d >= n) return;

    int beg = g_rowptr[d];
    int end = g_rowptr[d + 1];

    float4 acc = *(const float4*)&g_hs[(size_t)d * D + lane * 4];   // self loop

    int e = beg;
    for (; e + 1 < end; e += 2) {
        int s0 = g_csrc[e];
        int s1 = g_csrc[e + 1];
        float4 v0 = *(const float4*)&g_hs[(size_t)s0 * D + lane * 4];
        float4 v1 = *(const float4*)&g_hs[(size_t)s1 * D + lane * 4];
        acc.x += v0.x; acc.y += v0.y; acc.z += v0.z; acc.w += v0.w;
        acc.x += v1.x; acc.y += v1.y; acc.z += v1.z; acc.w += v1.w;
    }
    if (e < end) {
        int s0 = g_csrc[e];
        float4 v0 = *(const float4*)&g_hs[(size_t)s0 * D + lane * 4];
        acc.x += v0.x; acc.y += v0.y; acc.z += v0.z; acc.w += v0.w;
    }

    float sd = g_dinv[d];
    float4 bb = *(const float4*)&b[lane * 4];
    float4 o;
    o.x = fmaxf(fmaf(sd, acc.x, bb.x), 0.f);
    o.y = fmaxf(fmaf(sd, acc.y, bb.y), 0.f);
    o.z = fmaxf(fmaf(sd, acc.z, bb.z), 0.f);
    o.w = fmaxf(fmaf(sd, acc.w, bb.w), 0.f);

    size_t off = (size_t)d * D + lane * 4;
    if (to_hilo) {
        uint4 hv, lv;
        hilo(o.x, hv.x, lv.x);
        hilo(o.y, hv.y, lv.y);
        hilo(o.z, hv.z, lv.z);
        hilo(o.w, hv.w, lv.w);
        *(uint4*)&g_Xh[off] = hv;
        *(uint4*)&g_Xl[off] = lv;
    } else {
        *(float4*)&g_act[off] = o;
    }
}

// ---------------------------------------------------------------------------
// pool: one warp per node, v4 reduction into g_pool[batch[i]]
__global__ void pool_kernel(const int* __restrict__ batch, int n) {
    int warp = (blockIdx.x * blockDim.x + threadIdx.x) >> 5;
    int lane = threadIdx.x & 31;
    if (warp >= n) return;
    int g = batch[warp];
    float4 v = *(const float4*)&g_act[(size_t)warp * D + lane * 4];
    float* p = &g_pool[(size_t)g * D + lane * 4];
    asm volatile("red.global.add.v4.f32 [%0], {%1,%2,%3,%4};"
                 :: "l"(p), "f"(v.x), "f"(v.y), "f"(v.z), "f"(v.w) : "memory");
    if (lane == 0) atomicAdd(&g_cnt[g], 1.0f);
}

// classifier: out[g] = relu(pooled @ Wc + bc) @ Wo + bo
__global__ void classifier_kernel(const float* __restrict__ Wc,
                                  const float* __restrict__ bc,
                                  const float* __restrict__ Wo,
                                  const float* __restrict__ bo,
                                  float* __restrict__ out) {
    __shared__ float sm[H];
    __shared__ float ps[D];
    int g = blockIdx.x;
    int j = threadIdx.x;            // 0..63
    float inv = 1.0f / fmaxf(g_cnt[g], 1.0f);
    ps[j]      = g_pool[g * D + j]      * inv;
    ps[j + 64] = g_pool[g * D + j + 64] * inv;
    __syncthreads();
    float acc = bc[j];
#pragma unroll 8
    for (int k = 0; k < D; k++) acc = fmaf(ps[k], Wc[k * H + j], acc);
    float z = fmaxf(acc, 0.f);
    sm[j] = z * Wo[j];
    __syncthreads();
    for (int s = 32; s > 0; s >>= 1) {
        if (j < s) sm[j] += sm[j + s];
        __syncthreads();
    }
    if (j == 0) out[g] = sm[0] + bo[0];
}

// ---------------------------------------------------------------------------
extern "C" void kernel_launch(void* const* d_in, const int* in_sizes, int n_in,
                              void* d_out, int out_size) {
    const float* x    = (const float*)d_in[0];
    const int*   ei   = (const int*)d_in[1];    // int32 (jax x64 disabled)
    const int*   bat  = (const int*)d_in[2];    // int32
    const float* W1   = (const float*)d_in[3];
    const float* b1   = (const float*)d_in[4];
    const float* W2   = (const float*)d_in[5];
    const float* b2   = (const float*)d_in[6];
    const float* W3   = (const float*)d_in[7];
    const float* b3   = (const float*)d_in[8];
    const float* Wc   = (const float*)d_in[9];
    const float* bc   = (const float*)d_in[10];
    const float* Wo   = (const float*)d_in[11];
    const float* bo   = (const float*)d_in[12];
    float* out = (float*)d_out;

    const int n = in_sizes[0] / D;        // 50000
    const int E = in_sizes[1] / 2;        // 800000
    const int* src = ei;
    const int* dst = ei + E;
    const int nb = (n + 255) / 256;       // scan blocks (196)

    // CSR build + dinv
    {
        int tot = (G * D > n) ? G * D : n;
        init_kernel<<<(tot + 255) / 256, 256>>>(n);
        deg_kernel<<<(E + 255) / 256, 256>>>(dst, E);
        scan1_kernel<<<nb, 256>>>(n);          // also computes g_dinv
        scan3_kernel<<<nb, 256>>>(n, E);       // bsum prefix folded in
        fill_kernel<<<(E + 255) / 256, 256>>>(src, dst, E);
    }

    // one-time x -> tf32 hi/lo
    convert_x_kernel<<<(n * 32 + 255) / 256, 256>>>(x, n * 32);

    const int gemm_blocks   = (n + TM - 1) / TM;     // 782
    const int gather_blocks = (n * 32 + 255) / 256;

    const float* Ws[3] = {W1, W2, W3};
    const float* bs[3] = {b1, b2, b3};
    for (int l = 0; l < 3; l++) {
        convert_w_kernel<<<16, 256>>>(Ws[l]);        // 4096 float4
        gemm_scale_kernel<<<gemm_blocks, 128>>>(n);
        gather_act_kernel<<<gather_blocks, 256>>>(bs[l], n, l < 2 ? 1 : 0);
    }

    pool_kernel<<<(n * 32 + 255) / 256, 256>>>(bat, n);
    classifier_kernel<<<G, H>>>(Wc, bc, Wo, bo, out);
}

// round 15
// speedup vs baseline: 1.1259x; 1.1259x over previous
#include <cuda_runtime.h>
#include <cuda_bf16.h>
#include <cstdint>

// Problem constants
#define NMAX 50000
#define EMAX 800000
#define D    128
#define G    512
#define H    64
#define NB_MAX 256   // blocks in scan pass 1 (ceil(50000/256)=196)

// Scratch (static device globals — allowed; runtime alloc is not)
__device__ float    g_hs  [NMAX * D];   // (X@W) * dinv[row]
__device__ float    g_act [NMAX * D];   // relu(dinv*agg + b)
__device__ uint32_t g_Wh  [D * D];      // tf32 hi of current layer W
__device__ uint32_t g_Wl  [D * D];      // tf32 lo of current layer W
__device__ float    g_dinv[NMAX];
__device__ float    g_pool[G * D];
__device__ float    g_cnt [G];
// CSR build
__device__ int      g_indeg [NMAX];
__device__ int      g_rowptr[NMAX + 1];
__device__ int      g_cursor[NMAX];
__device__ int      g_csrc  [EMAX];     // src node ids grouped by dst
__device__ int      g_bsum  [NB_MAX];

// ---------------------------------------------------------------------------
// tf32 helpers (mma layout verified R9; split-precision verified R13)
__device__ __forceinline__ uint32_t f2tf32(float f) {
    uint32_t u;
    asm("cvt.rna.tf32.f32 %0, %1;" : "=r"(u) : "f"(f));
    return u;
}

__device__ __forceinline__ void hilo(float f, uint32_t& hi, uint32_t& lo) {
    hi = f2tf32(f);
    lo = f2tf32(f - __uint_as_float(hi));
}

__device__ __forceinline__ void mma_tf32(float c[4],
                                         uint32_t a0, uint32_t a1,
                                         uint32_t a2, uint32_t a3,
                                         uint32_t b0, uint32_t b1) {
    asm volatile(
        "mma.sync.aligned.m16n8k8.row.col.f32.tf32.tf32.f32 "
        "{%0,%1,%2,%3}, {%4,%5,%6,%7}, {%8,%9}, {%0,%1,%2,%3};"
        : "+f"(c[0]), "+f"(c[1]), "+f"(c[2]), "+f"(c[3])
        : "r"(a0), "r"(a1), "r"(a2), "r"(a3), "r"(b0), "r"(b1));
}

// ---------------------------------------------------------------------------
__global__ void init_kernel(int n) {
    int i = blockIdx.x * blockDim.x + threadIdx.x;
    if (i < n) { g_indeg[i] = 0; g_cursor[i] = 0; }
    if (i < G * D)  g_pool[i] = 0.0f;
    if (i < G)      g_cnt[i]  = 0.0f;
}

__global__ void deg_kernel(const int* __restrict__ dst, int E) {
    int e = blockIdx.x * blockDim.x + threadIdx.x;
    if (e < E) atomicAdd(&g_indeg[dst[e]], 1);
}

// ---- scan of g_indeg -> g_rowptr (dinv fused) -----------------------------
__device__ __forceinline__ int block_scan_excl(int v, int* total) {
    __shared__ int wsum[8];
    int t = threadIdx.x, lane = t & 31, w = t >> 5;
    int x = v;
#pragma unroll
    for (int o = 1; o < 32; o <<= 1) {
        int y = __shfl_up_sync(0xffffffffu, x, o);
        if (lane >= o) x += y;
    }
    if (lane == 31) wsum[w] = x;
    __syncthreads();
    if (w == 0) {
        int s = (lane < 8) ? wsum[lane] : 0;
#pragma unroll
        for (int o = 1; o < 8; o <<= 1) {
            int y = __shfl_up_sync(0xffffffffu, s, o);
            if (lane >= o) s += y;
        }
        if (lane < 8) wsum[lane] = s;
    }
    __syncthreads();
    int incl = x + (w > 0 ? wsum[w - 1] : 0);
    *total = wsum[7];
    return incl - v;
}

__global__ void scan1_kernel(int n) {
    int i = blockIdx.x * 256 + threadIdx.x;
    int v = (i < n) ? g_indeg[i] : 0;
    int total;
    int excl = block_scan_excl(v, &total);
    if (i < n) {
        g_rowptr[i] = excl;
        g_dinv[i] = rsqrtf((float)v + 1.0f);   // + self loop
    }
    if (threadIdx.x == 0) g_bsum[blockIdx.x] = total;
}

// scan3: each block reduces its own bsum prefix (merged scan2+scan3)
__global__ void scan3_kernel(int n, int E) {
    __shared__ int red[8];
    int bid = blockIdx.x, t = threadIdx.x, lane = t & 31, w = t >> 5;
    int partial = 0;
    for (int j = t; j < bid; j += 256) partial += g_bsum[j];
#pragma unroll
    for (int o = 16; o > 0; o >>= 1)
        partial += __shfl_down_sync(0xffffffffu, partial, o);
    if (lane == 0) red[w] = partial;
    __syncthreads();
    if (t == 0) {
        int s = 0;
#pragma unroll
        for (int j = 0; j < 8; j++) s += red[j];
        red[0] = s;
    }
    __syncthreads();
    int base = red[0];
    int i = bid * 256 + t;
    if (i < n) g_rowptr[i] += base;
    if (bid == 0 && t == 0) g_rowptr[n] = E;
}

__global__ void fill_kernel(const int* __restrict__ src,
                            const int* __restrict__ dst, int E) {
    int e = blockIdx.x * blockDim.x + threadIdx.x;
    if (e >= E) return;
    int d = dst[e];
    int pos = g_rowptr[d] + atomicAdd(&g_cursor[d], 1);
    g_csrc[pos] = src[e];
}

// ---------------------------------------------------------------------------
// per-layer W -> tf32 hi/lo (removes 782x redundant per-CTA conversion)
__global__ void convert_w_kernel(const float* __restrict__ W) {
    int i = blockIdx.x * blockDim.x + threadIdx.x;   // float4 index, 4096 tot
    float4 v = ((const float4*)W)[i];
    uint4 hv, lv;
    hilo(v.x, hv.x, lv.x);
    hilo(v.y, hv.y, lv.y);
    hilo(v.z, hv.z, lv.z);
    hilo(v.w, hv.w, lv.w);
    ((uint4*)g_Wh)[i] = hv;
    ((uint4*)g_Wl)[i] = lv;
}

// ---------------------------------------------------------------------------
// Split-precision 3xTF32 GEMM: g_hs = (X @ W) * dinv[row]
// W pre-converted to hi/lo (pure uint4 copy fill); X converted in-kernel
// (fp32 read keeps GMEM traffic at 25MB/layer — R14 showed hi/lo X regresses).
// Tile 64(M) x 128(N), 128 threads = 4 warps (2m x 2n), warp tile 32x64.
// K chunked by 16. Smem 25.6KB, occ 4 -> balanced waves (782 tiles/592 slots).
// use_act != 0 -> input is g_act (device symbol, resolved in device code).
#define TM 64
__global__ void __launch_bounds__(128, 4)
gemm_scale_kernel(const float* __restrict__ Xin, int n, int use_act) {
    const float* X = use_act ? (const float*)g_act : Xin;

    // strides 68/132 (== 4 mod 32): fragment LDS bank = 4*t4+tg, conflict-free
    __shared__ uint32_t Xh[16][68], Xl[16][68];     // [k][row] transposed
    __shared__ uint32_t Wh[16][132], Wl[16][132];   // [k][col]

    const int tid  = threadIdx.x;
    const int wid  = tid >> 5;
    const int lane = tid & 31;
    const int tg   = lane >> 2;        // 0..7
    const int t4   = lane & 3;         // 0..3
    const int mw   = wid & 1;          // 2 m-warps
    const int nw   = wid >> 1;         // 2 n-warps
    const int r_base = mw * 32;
    const int n_base = nw * 64;
    const int row0 = blockIdx.x * TM;

    float c[2][8][4];
#pragma unroll
    for (int mt = 0; mt < 2; mt++)
#pragma unroll
        for (int nt = 0; nt < 8; nt++)
#pragma unroll
            for (int i = 0; i < 4; i++) c[mt][nt][i] = 0.0f;

    for (int k0 = 0; k0 < 128; k0 += 16) {
        // X chunk: 64 rows x 16 k, transposed hi/lo: 256 float4
#pragma unroll
        for (int i = tid; i < 256; i += 128) {
            int r = i >> 2, q = i & 3;
            float4 v = make_float4(0.f, 0.f, 0.f, 0.f);
            if (row0 + r < n)
                v = *(const float4*)&X[(size_t)(row0 + r) * D + k0 + q * 4];
            uint32_t h, l;
            hilo(v.x, h, l); Xh[q * 4 + 0][r] = h; Xl[q * 4 + 0][r] = l;
            hilo(v.y, h, l); Xh[q * 4 + 1][r] = h; Xl[q * 4 + 1][r] = l;
            hilo(v.z, h, l); Xh[q * 4 + 2][r] = h; Xl[q * 4 + 2][r] = l;
            hilo(v.w, h, l); Xh[q * 4 + 3][r] = h; Xl[q * 4 + 3][r] = l;
        }
        // W chunk: 16 k x 128 cols; pure vector copies (pre-converted)
#pragma unroll
        for (int i = tid; i < 512; i += 128) {
            int rk = i >> 5, q = i & 31;
            size_t off = (size_t)(k0 + rk) * D + q * 4;
            *(uint4*)&Wh[rk][q * 4] = *(const uint4*)&g_Wh[off];
            *(uint4*)&Wl[rk][q * 4] = *(const uint4*)&g_Wl[off];
        }
        __syncthreads();

#pragma unroll
        for (int ks = 0; ks < 2; ks++) {
            const int kk = ks * 8 + t4;
            uint32_t ah[2][4], al[2][4];
#pragma unroll
            for (int mt = 0; mt < 2; mt++) {
                int r = r_base + mt * 16 + tg;
                ah[mt][0] = Xh[kk    ][r];     al[mt][0] = Xl[kk    ][r];
                ah[mt][1] = Xh[kk    ][r + 8]; al[mt][1] = Xl[kk    ][r + 8];
                ah[mt][2] = Xh[kk + 4][r];     al[mt][2] = Xl[kk + 4][r];
                ah[mt][3] = Xh[kk + 4][r + 8]; al[mt][3] = Xl[kk + 4][r + 8];
            }
#pragma unroll
            for (int nh = 0; nh < 2; nh++) {
                uint32_t bh[4][2], bl[4][2];
#pragma unroll
                for (int j = 0; j < 4; j++) {
                    int nn = n_base + (nh * 4 + j) * 8 + tg;
                    bh[j][0] = Wh[kk    ][nn]; bl[j][0] = Wl[kk    ][nn];
                    bh[j][1] = Wh[kk + 4][nn]; bl[j][1] = Wl[kk + 4][nn];
                }
#pragma unroll
                for (int mt = 0; mt < 2; mt++)
#pragma unroll
                    for (int j = 0; j < 4; j++) {
                        float* cc = c[mt][nh * 4 + j];
                        mma_tf32(cc, ah[mt][0], ah[mt][1], ah[mt][2], ah[mt][3],
                                 bh[j][0], bh[j][1]);
                        mma_tf32(cc, ah[mt][0], ah[mt][1], ah[mt][2], ah[mt][3],
                                 bl[j][0], bl[j][1]);
                        mma_tf32(cc, al[mt][0], al[mt][1], al[mt][2], al[mt][3],
                                 bh[j][0], bh[j][1]);
                    }
            }
        }
        __syncthreads();
    }

    // Epilogue: scale by dinv[row], write g_hs
#pragma unroll
    for (int mt = 0; mt < 2; mt++) {
        int rA = row0 + r_base + mt * 16 + tg;
        int rB = rA + 8;
        float sA = (rA < n) ? g_dinv[rA] : 0.0f;
        float sB = (rB < n) ? g_dinv[rB] : 0.0f;
#pragma unroll
        for (int nt = 0; nt < 8; nt++) {
            int col = n_base + nt * 8 + t4 * 2;
            if (rA < n)
                *(float2*)&g_hs[(size_t)rA * D + col] =
                    make_float2(c[mt][nt][0] * sA, c[mt][nt][1] * sA);
            if (rB < n)
                *(float2*)&g_hs[(size_t)rB * D + col] =
                    make_float2(c[mt][nt][2] * sB, c[mt][nt][3] * sB);
        }
    }
}

// ---------------------------------------------------------------------------
// Fused gather + activation (pull mode, no atomics):
// act[d] = relu(dinv[d] * (hs[d] + sum_{s in N(d)} hs[s]) + b)
__global__ void gather_act_kernel(const float* __restrict__ b, int n) {
    int d    = (blockIdx.x * blockDim.x + threadIdx.x) >> 5;
    int lane = threadIdx.x & 31;
    if (d >= n) return;

    int beg = g_rowptr[d];
    int end = g_rowptr[d + 1];

    float4 acc = *(const float4*)&g_hs[(size_t)d * D + lane * 4];   // self loop

    int e = beg;
    for (; e + 1 < end; e += 2) {
        int s0 = g_csrc[e];
        int s1 = g_csrc[e + 1];
        float4 v0 = *(const float4*)&g_hs[(size_t)s0 * D + lane * 4];
        float4 v1 = *(const float4*)&g_hs[(size_t)s1 * D + lane * 4];
        acc.x += v0.x; acc.y += v0.y; acc.z += v0.z; acc.w += v0.w;
        acc.x += v1.x; acc.y += v1.y; acc.z += v1.z; acc.w += v1.w;
    }
    if (e < end) {
        int s0 = g_csrc[e];
        float4 v0 = *(const float4*)&g_hs[(size_t)s0 * D + lane * 4];
        acc.x += v0.x; acc.y += v0.y; acc.z += v0.z; acc.w += v0.w;
    }

    float sd = g_dinv[d];
    float4 bb = *(const float4*)&b[lane * 4];
    float4 o;
    o.x = fmaxf(fmaf(sd, acc.x, bb.x), 0.f);
    o.y = fmaxf(fmaf(sd, acc.y, bb.y), 0.f);
    o.z = fmaxf(fmaf(sd, acc.z, bb.z), 0.f);
    o.w = fmaxf(fmaf(sd, acc.w, bb.w), 0.f);
    *(float4*)&g_act[(size_t)d * D + lane * 4] = o;
}

// ---------------------------------------------------------------------------
// pool: one warp per node, v4 reduction into g_pool[batch[i]]
__global__ void pool_kernel(const int* __restrict__ batch, int n) {
    int warp = (blockIdx.x * blockDim.x + threadIdx.x) >> 5;
    int lane = threadIdx.x & 31;
    if (warp >= n) return;
    int g = batch[warp];
    float4 v = *(const float4*)&g_act[(size_t)warp * D + lane * 4];
    float* p = &g_pool[(size_t)g * D + lane * 4];
    asm volatile("red.global.add.v4.f32 [%0], {%1,%2,%3,%4};"
                 :: "l"(p), "f"(v.x), "f"(v.y), "f"(v.z), "f"(v.w) : "memory");
    if (lane == 0) atomicAdd(&g_cnt[g], 1.0f);
}

// classifier: out[g] = relu(pooled @ Wc + bc) @ Wo + bo
__global__ void classifier_kernel(const float* __restrict__ Wc,
                                  const float* __restrict__ bc,
                                  const float* __restrict__ Wo,
                                  const float* __restrict__ bo,
                                  float* __restrict__ out) {
    __shared__ float sm[H];
    __shared__ float ps[D];
    int g = blockIdx.x;
    int j = threadIdx.x;            // 0..63
    float inv = 1.0f / fmaxf(g_cnt[g], 1.0f);
    ps[j]      = g_pool[g * D + j]      * inv;
    ps[j + 64] = g_pool[g * D + j + 64] * inv;
    __syncthreads();
    float acc = bc[j];
#pragma unroll 8
    for (int k = 0; k < D; k++) acc = fmaf(ps[k], Wc[k * H + j], acc);
    float z = fmaxf(acc, 0.f);
    sm[j] = z * Wo[j];
    __syncthreads();
    for (int s = 32; s > 0; s >>= 1) {
        if (j < s) sm[j] += sm[j + s];
        __syncthreads();
    }
    if (j == 0) out[g] = sm[0] + bo[0];
}

// ---------------------------------------------------------------------------
extern "C" void kernel_launch(void* const* d_in, const int* in_sizes, int n_in,
                              void* d_out, int out_size) {
    const float* x    = (const float*)d_in[0];
    const int*   ei   = (const int*)d_in[1];    // int32 (jax x64 disabled)
    const int*   bat  = (const int*)d_in[2];    // int32
    const float* W1   = (const float*)d_in[3];
    const float* b1   = (const float*)d_in[4];
    const float* W2   = (const float*)d_in[5];
    const float* b2   = (const float*)d_in[6];
    const float* W3   = (const float*)d_in[7];
    const float* b3   = (const float*)d_in[8];
    const float* Wc   = (const float*)d_in[9];
    const float* bc   = (const float*)d_in[10];
    const float* Wo   = (const float*)d_in[11];
    const float* bo   = (const float*)d_in[12];
    float* out = (float*)d_out;

    const int n = in_sizes[0] / D;        // 50000
    const int E = in_sizes[1] / 2;        // 800000
    const int* src = ei;
    const int* dst = ei + E;
    const int nb = (n + 255) / 256;       // scan blocks (196)

    // CSR build + dinv
    {
        int tot = (G * D > n) ? G * D : n;
        init_kernel<<<(tot + 255) / 256, 256>>>(n);
        deg_kernel<<<(E + 255) / 256, 256>>>(dst, E);
        scan1_kernel<<<nb, 256>>>(n);          // also computes g_dinv
        scan3_kernel<<<nb, 256>>>(n, E);       // bsum prefix folded in
        fill_kernel<<<(E + 255) / 256, 256>>>(src, dst, E);
    }

    const int gemm_blocks   = (n + TM - 1) / TM;     // 782
    const int gather_blocks = (n * 32 + 255) / 256;

    const float* Ws[3] = {W1, W2, W3};
    const float* bs[3] = {b1, b2, b3};
    for (int l = 0; l < 3; l++) {
        convert_w_kernel<<<16, 256>>>(Ws[l]);        // 4096 float4
        gemm_scale_kernel<<<gemm_blocks, 128>>>(x, n, l > 0 ? 1 : 0);
        gather_act_kernel<<<gather_blocks, 256>>>(bs[l], n);
    }

    pool_kernel<<<(n * 32 + 255) / 256, 256>>>(bat, n);
    classifier_kernel<<<G, H>>>(Wc, bc, Wo, bo, out);
}

// round 17
// speedup vs baseline: 1.1270x; 1.0010x over previous
#include <cuda_runtime.h>
#include <cuda_bf16.h>
#include <cstdint>

// Problem constants
#define NMAX 50000
#define EMAX 800000
#define D    128
#define G    512
#define H    64
#define NB_MAX 256   // blocks in scan pass 1 (ceil(50000/256)=196)

// Scratch (static device globals — allowed; runtime alloc is not)
__device__ float    g_hs  [NMAX * D];   // (X@W) * dinv[row]
__device__ float    g_act [NMAX * D];   // relu(dinv*agg + b)
// W packed per k-chunk in MMA-fragment order:
// g_Wp[chunk(8)][ks(2)][t4(4)][nn(128)] = {h(kk),h(kk+4),l(kk),l(kk+4)}
__device__ uint4    g_Wp  [8 * 2 * 4 * 128];
__device__ float    g_dinv[NMAX];
__device__ float    g_pool[G * D];
__device__ float    g_cnt [G];
// CSR build
__device__ int      g_indeg [NMAX];
__device__ int      g_rowptr[NMAX + 1];
__device__ int      g_cursor[NMAX];
__device__ int      g_csrc  [EMAX];     // src node ids grouped by dst
__device__ int      g_bsum  [NB_MAX];

// ---------------------------------------------------------------------------
// tf32 helpers (mma layout verified R9; split-precision verified R13)
__device__ __forceinline__ uint32_t f2tf32(float f) {
    uint32_t u;
    asm("cvt.rna.tf32.f32 %0, %1;" : "=r"(u) : "f"(f));
    return u;
}

__device__ __forceinline__ void hilo(float f, uint32_t& hi, uint32_t& lo) {
    hi = f2tf32(f);
    lo = f2tf32(f - __uint_as_float(hi));
}

__device__ __forceinline__ void mma_tf32(float c[4],
                                         uint32_t a0, uint32_t a1,
                                         uint32_t a2, uint32_t a3,
                                         uint32_t b0, uint32_t b1) {
    asm volatile(
        "mma.sync.aligned.m16n8k8.row.col.f32.tf32.tf32.f32 "
        "{%0,%1,%2,%3}, {%4,%5,%6,%7}, {%8,%9}, {%0,%1,%2,%3};"
        : "+f"(c[0]), "+f"(c[1]), "+f"(c[2]), "+f"(c[3])
        : "r"(a0), "r"(a1), "r"(a2), "r"(a3), "r"(b0), "r"(b1));
}

// ---------------------------------------------------------------------------
__global__ void init_kernel(int n) {
    int i = blockIdx.x * blockDim.x + threadIdx.x;
    if (i < n) { g_indeg[i] = 0; g_cursor[i] = 0; }
    if (i < G * D)  g_pool[i] = 0.0f;
    if (i < G)      g_cnt[i]  = 0.0f;
}

__global__ void deg_kernel(const int* __restrict__ dst, int E) {
    int e = blockIdx.x * blockDim.x + threadIdx.x;
    if (e < E) atomicAdd(&g_indeg[dst[e]], 1);
}

// ---- scan of g_indeg -> g_rowptr (dinv fused) -----------------------------
__device__ __forceinline__ int block_scan_excl(int v, int* total) {
    __shared__ int wsum[8];
    int t = threadIdx.x, lane = t & 31, w = t >> 5;
    int x = v;
#pragma unroll
    for (int o = 1; o < 32; o <<= 1) {
        int y = __shfl_up_sync(0xffffffffu, x, o);
        if (lane >= o) x += y;
    }
    if (lane == 31) wsum[w] = x;
    __syncthreads();
    if (w == 0) {
        int s = (lane < 8) ? wsum[lane] : 0;
#pragma unroll
        for (int o = 1; o < 8; o <<= 1) {
            int y = __shfl_up_sync(0xffffffffu, s, o);
            if (lane >= o) s += y;
        }
        if (lane < 8) wsum[lane] = s;
    }
    __syncthreads();
    int incl = x + (w > 0 ? wsum[w - 1] : 0);
    *total = wsum[7];
    return incl - v;
}

__global__ void scan1_kernel(int n) {
    int i = blockIdx.x * 256 + threadIdx.x;
    int v = (i < n) ? g_indeg[i] : 0;
    int total;
    int excl = block_scan_excl(v, &total);
    if (i < n) {
        g_rowptr[i] = excl;
        g_dinv[i] = rsqrtf((float)v + 1.0f);   // + self loop
    }
    if (threadIdx.x == 0) g_bsum[blockIdx.x] = total;
}

// scan3: each block reduces its own bsum prefix (merged scan2+scan3)
__global__ void scan3_kernel(int n, int E) {
    __shared__ int red[8];
    int bid = blockIdx.x, t = threadIdx.x, lane = t & 31, w = t >> 5;
    int partial = 0;
    for (int j = t; j < bid; j += 256) partial += g_bsum[j];
#pragma unroll
    for (int o = 16; o > 0; o >>= 1)
        partial += __shfl_down_sync(0xffffffffu, partial, o);
    if (lane == 0) red[w] = partial;
    __syncthreads();
    if (t == 0) {
        int s = 0;
#pragma unroll
        for (int j = 0; j < 8; j++) s += red[j];
        red[0] = s;
    }
    __syncthreads();
    int base = red[0];
    int i = bid * 256 + t;
    if (i < n) g_rowptr[i] += base;
    if (bid == 0 && t == 0) g_rowptr[n] = E;
}

__global__ void fill_kernel(const int* __restrict__ src,
                            const int* __restrict__ dst, int E) {
    int e = blockIdx.x * blockDim.x + threadIdx.x;
    if (e >= E) return;
    int d = dst[e];
    int pos = g_rowptr[d] + atomicAdd(&g_cursor[d], 1);
    g_csrc[pos] = src[e];
}

// ---------------------------------------------------------------------------
// per-layer W -> packed tf32 hi/lo fragments in GMEM.
// index i = ((chunk*2 + ks)*4 + t4)*128 + nn; kk = chunk*16 + ks*8 + t4
__global__ void convert_w_kernel(const float* __restrict__ W) {
    int i = blockIdx.x * blockDim.x + threadIdx.x;   // 0..8191
    int nn = i & 127;
    int t4 = (i >> 7) & 3;
    int ks = (i >> 9) & 1;
    int ch = i >> 10;
    int k1 = ch * 16 + ks * 8 + t4;
    int k2 = k1 + 4;
    uint4 p;
    hilo(W[k1 * D + nn], p.x, p.z);
    hilo(W[k2 * D + nn], p.y, p.w);
    g_Wp[i] = p;
}

// ---------------------------------------------------------------------------
// Split-precision 3xTF32 GEMM: g_hs = (X @ W) * dinv[row]
// Smem packed in MMA-fragment order: every fragment load is one LDS.128
// (inner-loop LDS count 768 scalar -> 192 vector per thread).
// Tile 64(M) x 128(N), 128 threads = 4 warps (2m x 2n), warp tile 32x64.
// K chunked by 16. Pads: t4-stride == 8 words mod 32 -> conflict-free LDS.128.
// use_act != 0 -> input is g_act (device symbol, resolved in device code).
#define TM 64
__global__ void __launch_bounds__(128, 4)
gemm_scale_kernel(const float* __restrict__ Xin, int n, int use_act) {
    const float* X = use_act ? (const float*)g_act : Xin;

    __shared__ uint4 Xp[2][4][66];    // [ks][t4][row]  {h0,h1,l0,l1}
    __shared__ uint4 Wp[2][4][130];   // [ks][t4][col]  {h0,h1,l0,l1}

    const int tid  = threadIdx.x;
    const int wid  = tid >> 5;
    const int lane = tid & 31;
    const int tg   = lane >> 2;        // 0..7
    const int t4   = lane & 3;         // 0..3
    const int mw   = wid & 1;          // 2 m-warps
    const int nw   = wid >> 1;         // 2 n-warps
    const int r_base = mw * 32;
    const int n_base = nw * 64;
    const int row0 = blockIdx.x * TM;

    // X fill decomposition: one (row, k-half) per thread
    const int fr = tid >> 1;           // 0..63 row
    const int fh = tid & 1;            // 0..1  k-half == ks

    float c[2][8][4];
#pragma unroll
    for (int mt = 0; mt < 2; mt++)
#pragma unroll
        for (int nt = 0; nt < 8; nt++)
#pragma unroll
            for (int i = 0; i < 4; i++) c[mt][nt][i] = 0.0f;

    for (int ch = 0; ch < 8; ch++) {
        const int k0 = ch * 16;
        // X chunk fill: load 8 fp32, convert, pack 4 uint4
        {
            float4 v0 = make_float4(0.f, 0.f, 0.f, 0.f);
            float4 v1 = v0;
            if (row0 + fr < n) {
                const float* xp = &X[(size_t)(row0 + fr) * D + k0 + fh * 8];
                v0 = *(const float4*)&xp[0];
                v1 = *(const float4*)&xp[4];
            }
            uint32_t h[8], l[8];
            hilo(v0.x, h[0], l[0]); hilo(v0.y, h[1], l[1]);
            hilo(v0.z, h[2], l[2]); hilo(v0.w, h[3], l[3]);
            hilo(v1.x, h[4], l[4]); hilo(v1.y, h[5], l[5]);
            hilo(v1.z, h[6], l[6]); hilo(v1.w, h[7], l[7]);
#pragma unroll
            for (int q = 0; q < 4; q++)
                Xp[fh][q][fr] = make_uint4(h[q], h[q + 4], l[q], l[q + 4]);
        }
        // W chunk fill: pure LDG.128 -> STS.128 copy of packed data
        {
            const uint4* wsrc = &g_Wp[ch * 1024];
#pragma unroll
            for (int i = tid; i < 1024; i += 128) {
                int ks = i >> 9, q4 = (i >> 7) & 3, nn = i & 127;
                Wp[ks][q4][nn] = wsrc[i];
            }
        }
        __syncthreads();

#pragma unroll
        for (int ks = 0; ks < 2; ks++) {
            // A fragments: 2 LDS.128 per m-tile
            uint32_t ah[2][4], al[2][4];
#pragma unroll
            for (int mt = 0; mt < 2; mt++) {
                int r = r_base + mt * 16 + tg;
                uint4 pa = Xp[ks][t4][r];
                uint4 pb = Xp[ks][t4][r + 8];
                ah[mt][0] = pa.x; ah[mt][1] = pb.x;
                ah[mt][2] = pa.y; ah[mt][3] = pb.y;
                al[mt][0] = pa.z; al[mt][1] = pb.z;
                al[mt][2] = pa.w; al[mt][3] = pb.w;
            }
#pragma unroll
            for (int nh = 0; nh < 2; nh++) {
                uint32_t bh[4][2], bl[4][2];
#pragma unroll
                for (int j = 0; j < 4; j++) {
                    int nn = n_base + (nh * 4 + j) * 8 + tg;
                    uint4 pw = Wp[ks][t4][nn];
                    bh[j][0] = pw.x; bh[j][1] = pw.y;
                    bl[j][0] = pw.z; bl[j][1] = pw.w;
                }
#pragma unroll
                for (int mt = 0; mt < 2; mt++)
#pragma unroll
                    for (int j = 0; j < 4; j++) {
                        float* cc = c[mt][nh * 4 + j];
                        mma_tf32(cc, ah[mt][0], ah[mt][1], ah[mt][2], ah[mt][3],
                                 bh[j][0], bh[j][1]);
                        mma_tf32(cc, ah[mt][0], ah[mt][1], ah[mt][2], ah[mt][3],
                                 bl[j][0], bl[j][1]);
                        mma_tf32(cc, al[mt][0], al[mt][1], al[mt][2], al[mt][3],
                                 bh[j][0], bh[j][1]);
                    }
            }
        }
        __syncthreads();
    }

    // Epilogue: scale by dinv[row], write g_hs
#pragma unroll
    for (int mt = 0; mt < 2; mt++) {
        int rA = row0 + r_base + mt * 16 + tg;
        int rB = rA + 8;
        float sA = (rA < n) ? g_dinv[rA] : 0.0f;
        float sB = (rB < n) ? g_dinv[rB] : 0.0f;
#pragma unroll
        for (int nt = 0; nt < 8; nt++) {
            int col = n_base + nt * 8 + t4 * 2;
            if (rA < n)
                *(float2*)&g_hs[(size_t)rA * D + col] =
                    make_float2(c[mt][nt][0] * sA, c[mt][nt][1] * sA);
            if (rB < n)
                *(float2*)&g_hs[(size_t)rB * D + col] =
                    make_float2(c[mt][nt][2] * sB, c[mt][nt][3] * sB);
        }
    }
}

// ---------------------------------------------------------------------------
// Fused gather + activation (pull mode, no atomics):
// act[d] = relu(dinv[d] * (hs[d] + sum_{s in N(d)} hs[s]) + b)
__global__ void gather_act_kernel(const float* __restrict__ b, int n) {
    int d    = (blockIdx.x * blockDim.x + threadIdx.x) >> 5;
    int lane = threadIdx.x & 31;
    if (d >= n) return;

    int beg = g_rowptr[d];
    int end = g_rowptr[d + 1];

    float4 acc = *(const float4*)&g_hs[(size_t)d * D + lane * 4];   // self loop

    int e = beg;
    for (; e + 1 < end; e += 2) {
        int s0 = g_csrc[e];
        int s1 = g_csrc[e + 1];
        float4 v0 = *(const float4*)&g_hs[(size_t)s0 * D + lane * 4];
        float4 v1 = *(const float4*)&g_hs[(size_t)s1 * D + lane * 4];
        acc.x += v0.x; acc.y += v0.y; acc.z += v0.z; acc.w += v0.w;
        acc.x += v1.x; acc.y += v1.y; acc.z += v1.z; acc.w += v1.w;
    }
    if (e < end) {
        int s0 = g_csrc[e];
        float4 v0 = *(const float4*)&g_hs[(size_t)s0 * D + lane * 4];
        acc.x += v0.x; acc.y += v0.y; acc.z += v0.z; acc.w += v0.w;
    }

    float sd = g_dinv[d];
    float4 bb = *(const float4*)&b[lane * 4];
    float4 o;
    o.x = fmaxf(fmaf(sd, acc.x, bb.x), 0.f);
    o.y = fmaxf(fmaf(sd, acc.y, bb.y), 0.f);
    o.z = fmaxf(fmaf(sd, acc.z, bb.z), 0.f);
    o.w = fmaxf(fmaf(sd, acc.w, bb.w), 0.f);
    *(float4*)&g_act[(size_t)d * D + lane * 4] = o;
}

// ---------------------------------------------------------------------------
// pool: one warp per node, v4 reduction into g_pool[batch[i]]
__global__ void pool_kernel(const int* __restrict__ batch, int n) {
    int warp = (blockIdx.x * blockDim.x + threadIdx.x) >> 5;
    int lane = threadIdx.x & 31;
    if (warp >= n) return;
    int g = batch[warp];
    float4 v = *(const float4*)&g_act[(size_t)warp * D + lane * 4];
    float* p = &g_pool[(size_t)g * D + lane * 4];
    asm volatile("red.global.add.v4.f32 [%0], {%1,%2,%3,%4};"
                 :: "l"(p), "f"(v.x), "f"(v.y), "f"(v.z), "f"(v.w) : "memory");
    if (lane == 0) atomicAdd(&g_cnt[g], 1.0f);
}

// classifier: out[g] = relu(pooled @ Wc + bc) @ Wo + bo
__global__ void classifier_kernel(const float* __restrict__ Wc,
                                  const float* __restrict__ bc,
                                  const float* __restrict__ Wo,
                                  const float* __restrict__ bo,
                                  float* __restrict__ out) {
    __shared__ float sm[H];
    __shared__ float ps[D];
    int g = blockIdx.x;
    int j = threadIdx.x;            // 0..63
    float inv = 1.0f / fmaxf(g_cnt[g], 1.0f);
    ps[j]      = g_pool[g * D + j]      * inv;
    ps[j + 64] = g_pool[g * D + j + 64] * inv;
    __syncthreads();
    float acc = bc[j];
#pragma unroll 8
    for (int k = 0; k < D; k++) acc = fmaf(ps[k], Wc[k * H + j], acc);
    float z = fmaxf(acc, 0.f);
    sm[j] = z * Wo[j];
    __syncthreads();
    for (int s = 32; s > 0; s >>= 1) {
        if (j < s) sm[j] += sm[j + s];
        __syncthreads();
    }
    if (j == 0) out[g] = sm[0] + bo[0];
}

// ---------------------------------------------------------------------------
extern "C" void kernel_launch(void* const* d_in, const int* in_sizes, int n_in,
                              void* d_out, int out_size) {
    const float* x    = (const float*)d_in[0];
    const int*   ei   = (const int*)d_in[1];    // int32 (jax x64 disabled)
    const int*   bat  = (const int*)d_in[2];    // int32
    const float* W1   = (const float*)d_in[3];
    const float* b1   = (const float*)d_in[4];
    const float* W2   = (const float*)d_in[5];
    const float* b2   = (const float*)d_in[6];
    const float* W3   = (const float*)d_in[7];
    const float* b3   = (const float*)d_in[8];
    const float* Wc   = (const float*)d_in[9];
    const float* bc   = (const float*)d_in[10];
    const float* Wo   = (const float*)d_in[11];
    const float* bo   = (const float*)d_in[12];
    float* out = (float*)d_out;

    const int n = in_sizes[0] / D;        // 50000
    const int E = in_sizes[1] / 2;        // 800000
    const int* src = ei;
    const int* dst = ei + E;
    const int nb = (n + 255) / 256;       // scan blocks (196)

    // CSR build + dinv
    {
        int tot = (G * D > n) ? G * D : n;
        init_kernel<<<(tot + 255) / 256, 256>>>(n);
        deg_kernel<<<(E + 255) / 256, 256>>>(dst, E);
        scan1_kernel<<<nb, 256>>>(n);          // also computes g_dinv
        scan3_kernel<<<nb, 256>>>(n, E);       // bsum prefix folded in
        fill_kernel<<<(E + 255) / 256, 256>>>(src, dst, E);
    }

    const int gemm_blocks   = (n + TM - 1) / TM;     // 782
    const int gather_blocks = (n * 32 + 255) / 256;

    const float* Ws[3] = {W1, W2, W3};
    const float* bs[3] = {b1, b2, b3};
    for (int l = 0; l < 3; l++) {
        convert_w_kernel<<<32, 256>>>(Ws[l]);        // 8192 packed uint4
        gemm_scale_kernel<<<gemm_blocks, 128>>>(x, n, l > 0 ? 1 : 0);
        gather_act_kernel<<<gather_blocks, 256>>>(bs[l], n);
    }

    pool_kernel<<<(n * 32 + 255) / 256, 256>>>(bat, n);
    classifier_kernel<<<G, H>>>(Wc, bc, Wo, bo, out);
}